// round 1
// baseline (speedup 1.0000x reference)
#include <cuda_runtime.h>

#define NQ    14
#define DEPTH 6
#define DIM   16384
#define TPB   512      // 9 thread bits
#define AMPS  32       // 5 local bits

typedef unsigned long long ull;

// ---------- packed f32x2 helpers (Blackwell double-rate fp32) ----------
__device__ __forceinline__ ull pack2(float x, float y){
    ull r; asm("mov.b64 %0,{%1,%2};" : "=l"(r) : "f"(x), "f"(y)); return r;
}
__device__ __forceinline__ void unpack2(ull v, float& x, float& y){
    asm("mov.b64 {%0,%1},%2;" : "=f"(x), "=f"(y) : "l"(v));
}
__device__ __forceinline__ ull f2mul(ull a, ull b){
    ull d; asm("mul.rn.f32x2 %0,%1,%2;" : "=l"(d) : "l"(a), "l"(b)); return d;
}
__device__ __forceinline__ ull f2fma(ull a, ull b, ull c){
    ull d; asm("fma.rn.f32x2 %0,%1,%2,%3;" : "=l"(d) : "l"(a), "l"(b), "l"(c)); return d;
}

// RY gate on register-local bit K: pairs (bit=0, bit=1), acting on both re & im lanes.
// new0 = c*a0 - s*a1 ; new1 = s*a0 + c*a1
template<int K>
__device__ __forceinline__ void gate(ull* a, ull cc, ull ss, ull nss){
#pragma unroll
    for (int m = 0; m < 16; m++){
        int lo = ((m >> K) << (K + 1)) | (m & ((1 << K) - 1));
        int hi = lo | (1 << K);
        ull a0 = a[lo], a1 = a[hi];
        a[lo] = f2fma(nss, a1, f2mul(cc, a0));
        a[hi] = f2fma(cc,  a1, f2mul(ss, a0));
    }
}

// ---------- layouts: which physical index bits are register-local ----------
// A: local = bits 0..4   : i = (t<<5) | l
// B: local = bits 5..9   : i = ((t>>5)<<10) | (l<<5) | (t&31)
// C: local = bits 9..13  : i = (l<<9) | t
__device__ __forceinline__ int mapA(int t, int l){ return (t << 5) | l; }
__device__ __forceinline__ int mapB(int t, int l){ return ((t >> 5) << 10) | (l << 5) | (t & 31); }
__device__ __forceinline__ int mapC(int t, int l){ return (l << 9) | t; }

#define PADI(i) ((i) + ((i) >> 5))   // conflict-avoiding smem padding

template<int FROM, int TO>
__device__ __forceinline__ void swapLayout(ull* buf, ull* amp, int t){
    __syncthreads();   // prior reads of buf done
#pragma unroll
    for (int l = 0; l < AMPS; l++){
        int i = (FROM == 0) ? mapA(t,l) : (FROM == 1) ? mapB(t,l) : mapC(t,l);
        buf[PADI(i)] = amp[l];
    }
    __syncthreads();
#pragma unroll
    for (int l = 0; l < AMPS; l++){
        int i = (TO == 0) ? mapA(t,l) : (TO == 1) ? mapB(t,l) : mapC(t,l);
        amp[l] = buf[PADI(i)];
    }
}

// CZ chain: sign = (-1)^popc(i & (i>>1)) over the 14-bit index. Pure diagonal -> flip
// both re & im sign bits in-register. LAY: 0 = layout A, 2 = layout C.
template<int LAY>
__device__ __forceinline__ void applyCZ(ull* amp, int t){
#pragma unroll
    for (int l = 0; l < AMPS; l++){
        int i = (LAY == 0) ? mapA(t,l) : mapC(t,l);
        if (__popc(i & (i >> 1)) & 1)
            amp[l] ^= 0x8000000080000000ULL;
    }
}

// smem float-region offsets (after the 16896-ull state buffer)
#define OFF_CX   0
#define OFF_SX   14
#define OFF_THC  28
#define OFF_THS  (28 + NQ*DEPTH)           // 112
#define OFF_RED  (OFF_THS + NQ*DEPTH)      // 196
#define OFF_ZF   (OFF_RED + 16*NQ)         // 420
#define N_FLOATS (OFF_ZF + NQ)             // 434
#define SMEM_BYTES ((16896u * 8u) + (N_FLOATS * 4u))

__global__ void __launch_bounds__(TPB, 1)
qc_kernel(const float* __restrict__ x,
          const float* __restrict__ theta,
          const float* __restrict__ head_w,
          const float* __restrict__ head_b,
          float* __restrict__ out)
{
    extern __shared__ ull sh[];
    ull*   buf = sh;                        // 16896 ull (padded 16384 state)
    float* fex = (float*)(sh + 16896);
    float* cx  = fex + OFF_CX;
    float* sx  = fex + OFF_SX;
    float* thc = fex + OFF_THC;
    float* ths = fex + OFF_THS;
    float* red = fex + OFF_RED;
    float* zf  = fex + OFF_ZF;

    const int t = threadIdx.x;
    const int b = blockIdx.x;

    // ----- per-sample RX angles + shared theta tables -----
    if (t < NQ){
        float h = 0.5f * x[b * NQ + t];
        cx[t] = cosf(h);
        sx[t] = sinf(h);
    }
    if (t < NQ * DEPTH){
        float h = 0.5f * theta[t];
        thc[t] = cosf(h);
        ths[t] = sinf(h);
    }
    __syncthreads();

    // ----- initial product state, layout A -----
    // amp(i) = r(i) * (-i)^popc(i), r(i) = prod_p (bit_p ? s[13-p] : c[13-p])
    ull amp[AMPS];
    float rT = 1.0f;
#pragma unroll
    for (int j = 0; j < 9; j++)
        rT *= ((t >> j) & 1) ? sx[8 - j] : cx[8 - j];   // phys bit 5+j -> qubit 8-j
    const int kT = __popc(t);
#pragma unroll
    for (int l = 0; l < AMPS; l++){
        float r = rT;
#pragma unroll
        for (int j = 0; j < 5; j++)
            r *= ((l >> j) & 1) ? sx[13 - j] : cx[13 - j];  // phys bit j -> qubit 13-j
        int k = (kT + __popc(l)) & 3;
        float re = (k == 0) ? r : ((k == 2) ? -r : 0.0f);
        float im = (k == 1) ? -r : ((k == 3) ? r : 0.0f);
        amp[l] = pack2(re, im);
    }

#define GATE(K, IDX) do { float c_ = thc[(IDX)], s_ = ths[(IDX)]; \
        gate<K>(amp, pack2(c_, c_), pack2(s_, s_), pack2(-s_, -s_)); } while (0)

    // ----- 6 layers, alternating sweep direction to avoid inter-layer swaps -----
#pragma unroll 1
    for (int d = 0; d < DEPTH; d += 2){
        int base = d * NQ;
        // even layer: A (bits 0-4) -> B (bits 5-9) -> C (bits 10-13), CZ in C
        GATE(0, base + 13); GATE(1, base + 12); GATE(2, base + 11); GATE(3, base + 10); GATE(4, base + 9);
        swapLayout<0, 1>(buf, amp, t);
        GATE(0, base + 8);  GATE(1, base + 7);  GATE(2, base + 6);  GATE(3, base + 5);  GATE(4, base + 4);
        swapLayout<1, 2>(buf, amp, t);
        GATE(1, base + 3);  GATE(2, base + 2);  GATE(3, base + 1);  GATE(4, base + 0);
        applyCZ<2>(amp, t);

        base += NQ;
        // odd layer: C (bits 10-13) -> B -> A, CZ in A
        GATE(1, base + 3);  GATE(2, base + 2);  GATE(3, base + 1);  GATE(4, base + 0);
        swapLayout<2, 1>(buf, amp, t);
        GATE(0, base + 8);  GATE(1, base + 7);  GATE(2, base + 6);  GATE(3, base + 5);  GATE(4, base + 4);
        swapLayout<1, 0>(buf, amp, t);
        GATE(0, base + 13); GATE(1, base + 12); GATE(2, base + 11); GATE(3, base + 10); GATE(4, base + 9);
        applyCZ<0>(amp, t);
    }
#undef GATE

    // ----- epilogue: probs -> per-bit Z expectations -> head GEMV -----
    // State is in layout A: i = (t<<5) | l.
    float S = 0.0f;
    float zl0 = 0.f, zl1 = 0.f, zl2 = 0.f, zl3 = 0.f, zl4 = 0.f;
#pragma unroll
    for (int l = 0; l < AMPS; l++){
        float re, im; unpack2(amp[l], re, im);
        float pr = fmaf(re, re, im * im);
        S += pr;
        zl0 += (l & 1)  ? -pr : pr;
        zl1 += (l & 2)  ? -pr : pr;
        zl2 += (l & 4)  ? -pr : pr;
        zl3 += (l & 8)  ? -pr : pr;
        zl4 += (l & 16) ? -pr : pr;
    }
    float z[NQ];
    z[0] = zl0; z[1] = zl1; z[2] = zl2; z[3] = zl3; z[4] = zl4;
#pragma unroll
    for (int j = 0; j < 9; j++)
        z[5 + j] = ((t >> j) & 1) ? -S : S;

#pragma unroll
    for (int off = 16; off; off >>= 1)
#pragma unroll
        for (int p = 0; p < NQ; p++)
            z[p] += __shfl_xor_sync(0xFFFFFFFFu, z[p], off);

    const int lane = t & 31, warp = t >> 5;
    __syncthreads();   // buf reads done; reuse small region is separate anyway
    if (lane == 0){
#pragma unroll
        for (int p = 0; p < NQ; p++) red[warp * NQ + p] = z[p];
    }
    __syncthreads();
    if (t < NQ){
        float a = 0.0f;
#pragma unroll
        for (int w = 0; w < TPB / 32; w++) a += red[w * NQ + t];
        zf[t] = a;
    }
    __syncthreads();
    if (t < 2){
        // logits[o] = head_b[o] + sum_p head_w[o][p] * Z_bit[p]
        float a = head_b[t];
#pragma unroll
        for (int p = 0; p < NQ; p++) a = fmaf(head_w[t * NQ + p], zf[p], a);
        out[b * 2 + t] = a;
    }
}

extern "C" void kernel_launch(void* const* d_in, const int* in_sizes, int n_in,
                              void* d_out, int out_size)
{
    const float* x      = (const float*)d_in[0];
    const float* theta  = (const float*)d_in[1];
    const float* head_w = (const float*)d_in[2];
    const float* head_b = (const float*)d_in[3];
    float* out = (float*)d_out;

    cudaFuncSetAttribute(qc_kernel, cudaFuncAttributeMaxDynamicSharedMemorySize, SMEM_BYTES);
    qc_kernel<<<512, TPB, SMEM_BYTES>>>(x, theta, head_w, head_b, out);
}

// round 2
// speedup vs baseline: 1.0802x; 1.0802x over previous
#include <cuda_runtime.h>

#define NQ    14
#define DEPTH 6
#define DIM   16384
#define TPB   512      // 9 thread bits
#define AMPS  32       // 5 local bits

#define ROWP  34                 // padded row stride (ull): conflict-free + 16B-aligned rows
#define SEG   (32 * ROWP)        // 1088 ull per warp segment
#define BUFN  (16 * SEG)         // 17408 ull state buffer

typedef unsigned long long ull;

// ---------- packed f32x2 helpers (Blackwell double-rate fp32) ----------
__device__ __forceinline__ ull pack2(float x, float y){
    ull r; asm("mov.b64 %0,{%1,%2};" : "=l"(r) : "f"(x), "f"(y)); return r;
}
__device__ __forceinline__ void unpack2(ull v, float& x, float& y){
    asm("mov.b64 {%0,%1},%2;" : "=f"(x), "=f"(y) : "l"(v));
}
__device__ __forceinline__ ull f2mul(ull a, ull b){
    ull d; asm("mul.rn.f32x2 %0,%1,%2;" : "=l"(d) : "l"(a), "l"(b)); return d;
}
__device__ __forceinline__ ull f2fma(ull a, ull b, ull c){
    ull d; asm("fma.rn.f32x2 %0,%1,%2,%3;" : "=l"(d) : "l"(a), "l"(b), "l"(c)); return d;
}

// RY gate on register-local bit K: new0 = c*a0 - s*a1 ; new1 = s*a0 + c*a1 (re & im lanes)
template<int K>
__device__ __forceinline__ void gate(ull* a, ull cc, ull ss, ull nss){
#pragma unroll
    for (int m = 0; m < 16; m++){
        int lo = ((m >> K) << (K + 1)) | (m & ((1 << K) - 1));
        int hi = lo | (1 << K);
        ull a0 = a[lo], a1 = a[hi];
        a[lo] = f2fma(nss, a1, f2mul(cc, a0));
        a[hi] = f2fma(cc,  a1, f2mul(ss, a0));
    }
}

// ---------- layouts: which physical index bits are register-local ----------
// A: local 0-4   : i = (t<<5) | l        (lane = bits 5-9, warp = bits 10-13)
// B: local 5-9   : i = ((t>>5)<<10) | (l<<5) | (t&31)   (lane = bits 0-4, warp = bits 10-13)
// C: local 9-13  : i = (l<<9) | t        (lane = bits 0-4, warp = bits 5-8)
__device__ __forceinline__ int mapA(int t, int l){ return (t << 5) | l; }
__device__ __forceinline__ int mapC(int t, int l){ return (l << 9) | t; }

// CZ chain: sign = (-1)^popc(i & (i>>1)); diagonal -> flip re/im sign bits in-register.
template<int LAY>   // 0 = layout A, 2 = layout C
__device__ __forceinline__ void applyCZ(ull* amp, int t){
#pragma unroll
    for (int l = 0; l < AMPS; l++){
        int i = (LAY == 0) ? mapA(t, l) : mapC(t, l);
        if (__popc(i & (i >> 1)) & 1)
            amp[l] ^= 0x8000000080000000ULL;
    }
}

// ---------- intra-warp 32x32 transpose (A<->B), warp-private tile, NO block barrier ----
// Store own row (contiguous, 128-bit), read own column (stride ROWP, conflict-free).
__device__ __forceinline__ void transposeAB(ull* buf, ull* amp, int t){
    ull* tile = buf + (t >> 5) * SEG;
    const int lane = t & 31;
    __syncwarp();
#pragma unroll
    for (int l = 0; l < AMPS; l += 2){
        ulonglong2 v; v.x = amp[l]; v.y = amp[l + 1];
        *reinterpret_cast<ulonglong2*>(tile + lane * ROWP + l) = v;
    }
    __syncwarp();
#pragma unroll
    for (int l = 0; l < AMPS; l++)
        amp[l] = tile[l * ROWP + lane];
}

// ---------- full swaps (one or two block barriers) --------------------------------
// padded address: i + 2*(i>>5)
// B addresses: warp w segment [SEG*w, SEG*w+1086]  -> addr = SEG*w + lane + ROWP*l
// C addresses: addr = 34*w + lane + 544*l          (cross-segment)
__device__ __forceinline__ void swapBtoC(ull* buf, ull* amp, int t){
    const int lane = t & 31, w = t >> 5;
    ull* segp = buf + SEG * w + lane;
    __syncwarp();                       // own-warp tile reads done (cross-lane)
#pragma unroll
    for (int l = 0; l < AMPS; l++) segp[ROWP * l] = amp[l];   // own segment only
    __syncthreads();
    ull* cp = buf + 34 * w + lane;
#pragma unroll
    for (int l = 0; l < AMPS; l++) amp[l] = cp[544 * l];
}

__device__ __forceinline__ void swapCtoB(ull* buf, ull* amp, int t){
    const int lane = t & 31, w = t >> 5;
    __syncthreads();                    // all warps' prior cross-segment reads done
    ull* cp = buf + 34 * w + lane;
#pragma unroll
    for (int l = 0; l < AMPS; l++) cp[544 * l] = amp[l];
    __syncthreads();
    ull* segp = buf + SEG * w + lane;
#pragma unroll
    for (int l = 0; l < AMPS; l++) amp[l] = segp[ROWP * l];   // own segment only
}

// smem float-region offsets (after the BUFN-ull state buffer)
#define OFF_CX   0
#define OFF_SX   14
#define OFF_THC  28
#define OFF_THS  (28 + NQ*DEPTH)           // 112
#define OFF_RED  (OFF_THS + NQ*DEPTH)      // 196
#define OFF_ZF   (OFF_RED + 16*NQ)         // 420
#define N_FLOATS (OFF_ZF + NQ)             // 434
#define SMEM_BYTES ((unsigned)(BUFN * 8u) + (N_FLOATS * 4u))

__global__ void __launch_bounds__(TPB, 1)
qc_kernel(const float* __restrict__ x,
          const float* __restrict__ theta,
          const float* __restrict__ head_w,
          const float* __restrict__ head_b,
          float* __restrict__ out)
{
    extern __shared__ ull sh[];
    ull*   buf = sh;                        // BUFN ull
    float* fex = (float*)(sh + BUFN);
    float* cx  = fex + OFF_CX;
    float* sx  = fex + OFF_SX;
    float* thc = fex + OFF_THC;
    float* ths = fex + OFF_THS;
    float* red = fex + OFF_RED;
    float* zf  = fex + OFF_ZF;

    const int t = threadIdx.x;
    const int b = blockIdx.x;

    // ----- per-sample RX angles + shared theta tables -----
    if (t < NQ){
        float h = 0.5f * x[b * NQ + t];
        cx[t] = cosf(h);
        sx[t] = sinf(h);
    }
    if (t < NQ * DEPTH){
        float h = 0.5f * theta[t];
        thc[t] = cosf(h);
        ths[t] = sinf(h);
    }
    __syncthreads();

    // ----- initial product state, layout A -----
    // amp(i) = r(i) * (-i)^popc(i), r(i) = prod_p (bit_p ? s[13-p] : c[13-p])
    ull amp[AMPS];
    float rT = 1.0f;
#pragma unroll
    for (int j = 0; j < 9; j++)
        rT *= ((t >> j) & 1) ? sx[8 - j] : cx[8 - j];   // phys bit 5+j -> qubit 8-j
    const int kT = __popc(t);
#pragma unroll
    for (int l = 0; l < AMPS; l++){
        float r = rT;
#pragma unroll
        for (int j = 0; j < 5; j++)
            r *= ((l >> j) & 1) ? sx[13 - j] : cx[13 - j];  // phys bit j -> qubit 13-j
        int k = (kT + __popc(l)) & 3;
        float re = (k == 0) ? r : ((k == 2) ? -r : 0.0f);
        float im = (k == 1) ? -r : ((k == 3) ? r : 0.0f);
        amp[l] = pack2(re, im);
    }

#define GATE(K, IDX) do { float c_ = thc[(IDX)], s_ = ths[(IDX)]; \
        gate<K>(amp, pack2(c_, c_), pack2(s_, s_), pack2(-s_, -s_)); } while (0)

    // ----- 6 layers; per layer: 1 intra-warp transpose + 1 full swap -----
#pragma unroll 1
    for (int d = 0; d < DEPTH; d += 2){
        int base = d * NQ;
        // even layer: A (bits 0-4) -> [warp transpose] -> B (bits 5-9) -> [swap] -> C (10-13)
        GATE(0, base + 13); GATE(1, base + 12); GATE(2, base + 11); GATE(3, base + 10); GATE(4, base + 9);
        transposeAB(buf, amp, t);
        GATE(0, base + 8);  GATE(1, base + 7);  GATE(2, base + 6);  GATE(3, base + 5);  GATE(4, base + 4);
        swapBtoC(buf, amp, t);
        GATE(1, base + 3);  GATE(2, base + 2);  GATE(3, base + 1);  GATE(4, base + 0);
        applyCZ<2>(amp, t);

        base += NQ;
        // odd layer: C (bits 9-13) -> [swap] -> B (bits 5-8) -> [warp transpose] -> A (0-4)
        GATE(0, base + 4);  GATE(1, base + 3);  GATE(2, base + 2);  GATE(3, base + 1);  GATE(4, base + 0);
        swapCtoB(buf, amp, t);
        GATE(0, base + 8);  GATE(1, base + 7);  GATE(2, base + 6);  GATE(3, base + 5);
        transposeAB(buf, amp, t);
        GATE(0, base + 13); GATE(1, base + 12); GATE(2, base + 11); GATE(3, base + 10); GATE(4, base + 9);
        applyCZ<0>(amp, t);
    }
#undef GATE

    // ----- epilogue: probs -> per-bit Z expectations -> head GEMV -----
    // State is in layout A: i = (t<<5) | l.
    float S = 0.0f;
    float zl0 = 0.f, zl1 = 0.f, zl2 = 0.f, zl3 = 0.f, zl4 = 0.f;
#pragma unroll
    for (int l = 0; l < AMPS; l++){
        float re, im; unpack2(amp[l], re, im);
        float pr = fmaf(re, re, im * im);
        S += pr;
        zl0 += (l & 1)  ? -pr : pr;
        zl1 += (l & 2)  ? -pr : pr;
        zl2 += (l & 4)  ? -pr : pr;
        zl3 += (l & 8)  ? -pr : pr;
        zl4 += (l & 16) ? -pr : pr;
    }
    float z[NQ];
    z[0] = zl0; z[1] = zl1; z[2] = zl2; z[3] = zl3; z[4] = zl4;
#pragma unroll
    for (int j = 0; j < 9; j++)
        z[5 + j] = ((t >> j) & 1) ? -S : S;

#pragma unroll
    for (int off = 16; off; off >>= 1)
#pragma unroll
        for (int p = 0; p < NQ; p++)
            z[p] += __shfl_xor_sync(0xFFFFFFFFu, z[p], off);

    const int lane = t & 31, warp = t >> 5;
    if (lane == 0){
#pragma unroll
        for (int p = 0; p < NQ; p++) red[warp * NQ + p] = z[p];
    }
    __syncthreads();
    if (t < NQ){
        float a = 0.0f;
#pragma unroll
        for (int w = 0; w < TPB / 32; w++) a += red[w * NQ + t];
        zf[t] = a;
    }
    __syncthreads();
    if (t < 2){
        // logits[o] = head_b[o] + sum_p head_w[o][p] * Z_bit[p]
        float a = head_b[t];
#pragma unroll
        for (int p = 0; p < NQ; p++) a = fmaf(head_w[t * NQ + p], zf[p], a);
        out[b * 2 + t] = a;
    }
}

extern "C" void kernel_launch(void* const* d_in, const int* in_sizes, int n_in,
                              void* d_out, int out_size)
{
    const float* x      = (const float*)d_in[0];
    const float* theta  = (const float*)d_in[1];
    const float* head_w = (const float*)d_in[2];
    const float* head_b = (const float*)d_in[3];
    float* out = (float*)d_out;

    cudaFuncSetAttribute(qc_kernel, cudaFuncAttributeMaxDynamicSharedMemorySize, SMEM_BYTES);
    qc_kernel<<<512, TPB, SMEM_BYTES>>>(x, theta, head_w, head_b, out);
}

// round 3
// speedup vs baseline: 1.1566x; 1.0707x over previous
#include <cuda_runtime.h>

#define NQ    14
#define DEPTH 6
#define DIM   16384
#define TPB   512      // 9 thread bits
#define AMPS  32       // 5 local bits

#define ROWP  34                 // padded row stride (ull): conflict-free + 16B-aligned rows
#define SEG   (32 * ROWP)        // 1088 ull per warp segment
#define BUFN  (16 * SEG)         // 17408 ull state buffer

typedef unsigned long long ull;

// ---------- packed f32x2 helpers (Blackwell double-rate fp32) ----------
__device__ __forceinline__ ull pack2(float x, float y){
    ull r; asm("mov.b64 %0,{%1,%2};" : "=l"(r) : "f"(x), "f"(y)); return r;
}
__device__ __forceinline__ void unpack2(ull v, float& x, float& y){
    asm("mov.b64 {%0,%1},%2;" : "=f"(x), "=f"(y) : "l"(v));
}
__device__ __forceinline__ ull f2fma(ull a, ull b, ull c){
    ull d; asm("fma.rn.f32x2 %0,%1,%2,%3;" : "=l"(d) : "l"(a), "l"(b), "l"(c)); return d;
}

// RY gate on register-local bit K via Paeth 3-shear rotation:
//   lo -= T*hi ; hi += S*lo ; lo -= T*hi   (T = tan(phi/2), S = sin(phi))
// == [lo' = c*lo - s*hi ; hi' = s*lo + c*hi], applied to re & im lanes packed.
template<int K>
__device__ __forceinline__ void gate(ull* a, ull nT, ull S){
#pragma unroll
    for (int m = 0; m < 16; m++){
        int lo = ((m >> K) << (K + 1)) | (m & ((1 << K) - 1));
        int hi = lo | (1 << K);
        ull a0 = a[lo], a1 = a[hi];
        a0 = f2fma(nT, a1, a0);
        a1 = f2fma(S,  a0, a1);
        a0 = f2fma(nT, a1, a0);
        a[lo] = a0; a[hi] = a1;
    }
}

// ---------- layouts: which physical index bits are register-local ----------
// A: local 0-4   : i = (t<<5) | l        (lane = bits 5-9, warp = bits 10-13)
// B: local 5-9   : i = ((t>>5)<<10) | (l<<5) | (t&31)   (lane = bits 0-4, warp = bits 10-13)
// C: local 9-13  : i = (l<<9) | t        (lane = bits 0-4, warp = bits 5-8)
__device__ __forceinline__ int mapA(int t, int l){ return (t << 5) | l; }
__device__ __forceinline__ int mapC(int t, int l){ return (l << 9) | t; }

// CZ chain: sign = (-1)^popc(i & (i>>1)); diagonal -> flip re/im sign bits in-register.
// Parity masks per thread are precomputed once (bit l of mask = flip amp[l]).
__device__ __forceinline__ void applyCZ(ull* amp, unsigned mask){
#pragma unroll
    for (int l = 0; l < AMPS; l++){
        if ((mask >> l) & 1u)
            amp[l] ^= 0x8000000080000000ULL;
    }
}

// ---------- intra-warp 32x32 transpose (A<->B), warp-private tile, NO block barrier ----
__device__ __forceinline__ void transposeAB(ull* buf, ull* amp, int t){
    ull* tile = buf + (t >> 5) * SEG;
    const int lane = t & 31;
    __syncwarp();
#pragma unroll
    for (int l = 0; l < AMPS; l += 2){
        ulonglong2 v; v.x = amp[l]; v.y = amp[l + 1];
        *reinterpret_cast<ulonglong2*>(tile + lane * ROWP + l) = v;
    }
    __syncwarp();
#pragma unroll
    for (int l = 0; l < AMPS; l++)
        amp[l] = tile[l * ROWP + lane];
}

// ---------- full swaps --------------------------------
// padded address: i + 2*(i>>5)
// B addresses: warp w segment -> addr = SEG*w + lane + ROWP*l
// C addresses: addr = 34*w + lane + 544*l   (cross-segment)
__device__ __forceinline__ void swapBtoC(ull* buf, ull* amp, int t){
    const int lane = t & 31, w = t >> 5;
    ull* segp = buf + SEG * w + lane;
    __syncwarp();                       // own-warp tile reads done (cross-lane)
#pragma unroll
    for (int l = 0; l < AMPS; l++) segp[ROWP * l] = amp[l];   // own segment only
    __syncthreads();
    ull* cp = buf + 34 * w + lane;
#pragma unroll
    for (int l = 0; l < AMPS; l++) amp[l] = cp[544 * l];
}

__device__ __forceinline__ void swapCtoB(ull* buf, ull* amp, int t){
    const int lane = t & 31, w = t >> 5;
    __syncthreads();                    // all warps' prior cross-segment reads done
    ull* cp = buf + 34 * w + lane;
#pragma unroll
    for (int l = 0; l < AMPS; l++) cp[544 * l] = amp[l];
    __syncthreads();
    ull* segp = buf + SEG * w + lane;
#pragma unroll
    for (int l = 0; l < AMPS; l++) amp[l] = segp[ROWP * l];   // own segment only
}

// smem float-region offsets (after the BUFN-ull state buffer)
#define OFF_CX   0
#define OFF_SX   14
#define OFF_THT  28                        // -tan(theta/4) table
#define OFF_THS  (28 + NQ*DEPTH)           // sin(theta/2) table
#define OFF_RED  (OFF_THS + NQ*DEPTH)      // 196
#define OFF_ZF   (OFF_RED + 16*NQ)         // 420
#define N_FLOATS (OFF_ZF + NQ)             // 434
#define SMEM_BYTES ((unsigned)(BUFN * 8u) + (N_FLOATS * 4u))

__global__ void __launch_bounds__(TPB, 1)
qc_kernel(const float* __restrict__ x,
          const float* __restrict__ theta,
          const float* __restrict__ head_w,
          const float* __restrict__ head_b,
          float* __restrict__ out)
{
    extern __shared__ ull sh[];
    ull*   buf = sh;                        // BUFN ull
    float* fex = (float*)(sh + BUFN);
    float* cx  = fex + OFF_CX;
    float* sx  = fex + OFF_SX;
    float* tht = fex + OFF_THT;
    float* ths = fex + OFF_THS;
    float* red = fex + OFF_RED;
    float* zf  = fex + OFF_ZF;

    const int t = threadIdx.x;
    const int b = blockIdx.x;

    // ----- per-sample RX angles + shared shear tables -----
    if (t < NQ){
        float h = 0.5f * x[b * NQ + t];
        cx[t] = cosf(h);
        sx[t] = sinf(h);
    }
    if (t < NQ * DEPTH){
        float th = theta[t];
        tht[t] = -tanf(0.25f * th);      // -T
        ths[t] =  sinf(0.50f * th);      //  S
    }

    // ----- precompute CZ parity masks (layout A and C) -----
    unsigned czA = 0, czC = 0;
#pragma unroll
    for (int l = 0; l < AMPS; l++){
        int iA = (t << 5) | l;
        int iC = (l << 9) | t;
        czA |= (unsigned)(__popc(iA & (iA >> 1)) & 1) << l;
        czC |= (unsigned)(__popc(iC & (iC >> 1)) & 1) << l;
    }
    __syncthreads();

    // ----- initial product state, layout A -----
    // amp(i) = r(i) * (-i)^popc(i), r(i) = prod_p (bit_p ? s[13-p] : c[13-p])
    ull amp[AMPS];
    float rT = 1.0f;
#pragma unroll
    for (int j = 0; j < 9; j++)
        rT *= ((t >> j) & 1) ? sx[8 - j] : cx[8 - j];   // phys bit 5+j -> qubit 8-j
    const int kT = __popc(t);
#pragma unroll
    for (int l = 0; l < AMPS; l++){
        float r = rT;
#pragma unroll
        for (int j = 0; j < 5; j++)
            r *= ((l >> j) & 1) ? sx[13 - j] : cx[13 - j];  // phys bit j -> qubit 13-j
        int k = (kT + __popc(l)) & 3;
        float re = (k == 0) ? r : ((k == 2) ? -r : 0.0f);
        float im = (k == 1) ? -r : ((k == 3) ? r : 0.0f);
        amp[l] = pack2(re, im);
    }

#define GATE(K, IDX) do { float nt_ = tht[(IDX)], s_ = ths[(IDX)]; \
        gate<K>(amp, pack2(nt_, nt_), pack2(s_, s_)); } while (0)

    // ----- 6 layers; per layer: 1 intra-warp transpose + 1 full swap -----
#pragma unroll 1
    for (int d = 0; d < DEPTH; d += 2){
        int base = d * NQ;
        // even layer: A (bits 0-4) -> [warp transpose] -> B (bits 5-9) -> [swap] -> C (10-13)
        GATE(0, base + 13); GATE(1, base + 12); GATE(2, base + 11); GATE(3, base + 10); GATE(4, base + 9);
        transposeAB(buf, amp, t);
        GATE(0, base + 8);  GATE(1, base + 7);  GATE(2, base + 6);  GATE(3, base + 5);  GATE(4, base + 4);
        swapBtoC(buf, amp, t);
        GATE(1, base + 3);  GATE(2, base + 2);  GATE(3, base + 1);  GATE(4, base + 0);
        applyCZ(amp, czC);

        base += NQ;
        // odd layer: C (bits 9-13) -> [swap] -> B (bits 5-8) -> [warp transpose] -> A (0-4)
        GATE(0, base + 4);  GATE(1, base + 3);  GATE(2, base + 2);  GATE(3, base + 1);  GATE(4, base + 0);
        swapCtoB(buf, amp, t);
        GATE(0, base + 8);  GATE(1, base + 7);  GATE(2, base + 6);  GATE(3, base + 5);
        transposeAB(buf, amp, t);
        GATE(0, base + 13); GATE(1, base + 12); GATE(2, base + 11); GATE(3, base + 10); GATE(4, base + 9);
        applyCZ(amp, czA);
    }
#undef GATE

    // ----- epilogue: probs -> per-bit Z expectations -> head GEMV -----
    // State is in layout A: i = (t<<5) | l.
    float S = 0.0f;
    float zl0 = 0.f, zl1 = 0.f, zl2 = 0.f, zl3 = 0.f, zl4 = 0.f;
#pragma unroll
    for (int l = 0; l < AMPS; l++){
        float re, im; unpack2(amp[l], re, im);
        float pr = fmaf(re, re, im * im);
        S += pr;
        zl0 += (l & 1)  ? -pr : pr;
        zl1 += (l & 2)  ? -pr : pr;
        zl2 += (l & 4)  ? -pr : pr;
        zl3 += (l & 8)  ? -pr : pr;
        zl4 += (l & 16) ? -pr : pr;
    }
    float z[NQ];
    z[0] = zl0; z[1] = zl1; z[2] = zl2; z[3] = zl3; z[4] = zl4;
#pragma unroll
    for (int j = 0; j < 9; j++)
        z[5 + j] = ((t >> j) & 1) ? -S : S;

#pragma unroll
    for (int off = 16; off; off >>= 1)
#pragma unroll
        for (int p = 0; p < NQ; p++)
            z[p] += __shfl_xor_sync(0xFFFFFFFFu, z[p], off);

    const int lane = t & 31, warp = t >> 5;
    if (lane == 0){
#pragma unroll
        for (int p = 0; p < NQ; p++) red[warp * NQ + p] = z[p];
    }
    __syncthreads();
    if (t < NQ){
        float a = 0.0f;
#pragma unroll
        for (int w = 0; w < TPB / 32; w++) a += red[w * NQ + t];
        zf[t] = a;
    }
    __syncthreads();
    if (t < 2){
        // logits[o] = head_b[o] + sum_p head_w[o][p] * Z_bit[p]
        float a = head_b[t];
#pragma unroll
        for (int p = 0; p < NQ; p++) a = fmaf(head_w[t * NQ + p], zf[p], a);
        out[b * 2 + t] = a;
    }
}

extern "C" void kernel_launch(void* const* d_in, const int* in_sizes, int n_in,
                              void* d_out, int out_size)
{
    const float* x      = (const float*)d_in[0];
    const float* theta  = (const float*)d_in[1];
    const float* head_w = (const float*)d_in[2];
    const float* head_b = (const float*)d_in[3];
    float* out = (float*)d_out;

    cudaFuncSetAttribute(qc_kernel, cudaFuncAttributeMaxDynamicSharedMemorySize, SMEM_BYTES);
    qc_kernel<<<512, TPB, SMEM_BYTES>>>(x, theta, head_w, head_b, out);
}

// round 4
// speedup vs baseline: 1.1568x; 1.0002x over previous
#include <cuda_runtime.h>

#define NQ    14
#define DEPTH 6
#define DIM   16384
#define TPB   512      // 9 thread bits
#define AMPS  32       // 5 local bits

#define ROWP  34                 // padded row stride (ull): conflict-free + 16B-aligned rows
#define SEG   (32 * ROWP)        // 1088 ull per warp segment
#define BUFN  (16 * SEG)         // 17408 ull state buffer

typedef unsigned long long ull;

// ---------- packed f32x2 helpers ----------
__device__ __forceinline__ ull pack2(float x, float y){
    ull r; asm("mov.b64 %0,{%1,%2};" : "=l"(r) : "f"(x), "f"(y)); return r;
}
__device__ __forceinline__ void unpack2(ull v, float& x, float& y){
    asm("mov.b64 {%0,%1},%2;" : "=f"(x), "=f"(y) : "l"(v));
}
__device__ __forceinline__ ull f2fma(ull a, ull b, ull c){
    ull d; asm("fma.rn.f32x2 %0,%1,%2,%3;" : "=l"(d) : "l"(a), "l"(b), "l"(c)); return d;
}

// RY gate on register-local bit K via Paeth 3-shear rotation:
//   lo -= T*hi ; hi += S*lo ; lo -= T*hi   (T = tan(phi/2), S = sin(phi))
template<int K>
__device__ __forceinline__ void gate(ull* a, ull nT, ull S){
#pragma unroll
    for (int m = 0; m < 16; m++){
        int lo = ((m >> K) << (K + 1)) | (m & ((1 << K) - 1));
        int hi = lo | (1 << K);
        ull a0 = a[lo], a1 = a[hi];
        a0 = f2fma(nT, a1, a0);
        a1 = f2fma(S,  a0, a1);
        a0 = f2fma(nT, a1, a0);
        a[lo] = a0; a[hi] = a1;
    }
}

// Same gate restricted to the 16 amps whose local bit SEL == PV (K != SEL).
template<int K, int SEL, int PV>
__device__ __forceinline__ void gate_half(ull* a, ull nT, ull S){
#pragma unroll
    for (int m = 0; m < 8; m++){
        int lo = PV << SEL;
        int mm = m;
#pragma unroll
        for (int p = 0; p < 5; p++){
            if (p != K && p != SEL){ lo |= (mm & 1) << p; mm >>= 1; }
        }
        int hi = lo | (1 << K);
        ull a0 = a[lo], a1 = a[hi];
        a0 = f2fma(nT, a1, a0);
        a1 = f2fma(S,  a0, a1);
        a0 = f2fma(nT, a1, a0);
        a[lo] = a0; a[hi] = a1;
    }
}

// ---------- layouts ----------
// A: local 0-4   : i = (t<<5) | l        (lane = bits 5-9, warp = bits 10-13)
// B: local 5-9   : i = ((t>>5)<<10) | (l<<5) | (t&31)   (l bit4 <-> phys bit 9)
// C: local 9-13  : i = (l<<9) | t        (l bit0 <-> phys bit 9)
__device__ __forceinline__ int mapA(int t, int l){ return (t << 5) | l; }
__device__ __forceinline__ int mapC(int t, int l){ return (l << 9) | t; }

// CZ chain: sign = (-1)^popc(i & (i>>1)); diagonal -> flip re/im sign bits in-register.
__device__ __forceinline__ void applyCZ(ull* amp, unsigned mask){
#pragma unroll
    for (int l = 0; l < AMPS; l++){
        if ((mask >> l) & 1u)
            amp[l] ^= 0x8000000080000000ULL;
    }
}

// ---------- intra-warp 32x32 transpose (A<->B), warp-private tile, NO block barrier ----
__device__ __forceinline__ void transposeAB(ull* buf, ull* amp, int t){
    ull* tile = buf + (t >> 5) * SEG;
    const int lane = t & 31;
    __syncwarp();
#pragma unroll
    for (int l = 0; l < AMPS; l += 2){
        ulonglong2 v; v.x = amp[l]; v.y = amp[l + 1];
        *reinterpret_cast<ulonglong2*>(tile + lane * ROWP + l) = v;
    }
    __syncwarp();
#pragma unroll
    for (int l = 0; l < AMPS; l++)
        amp[l] = tile[l * ROWP + lane];
}

// smem float-region offsets (after the BUFN-ull state buffer)
#define OFF_CX   0
#define OFF_SX   14
#define OFF_THT  28                        // -tan(theta/4) table
#define OFF_THS  (28 + NQ*DEPTH)           // sin(theta/2) table
#define OFF_RED  (OFF_THS + NQ*DEPTH)      // 196
#define OFF_ZF   (OFF_RED + 16*NQ)         // 420
#define N_FLOATS (OFF_ZF + NQ)             // 434
#define SMEM_BYTES ((unsigned)(BUFN * 8u) + (N_FLOATS * 4u))

__global__ void __launch_bounds__(TPB, 1)
qc_kernel(const float* __restrict__ x,
          const float* __restrict__ theta,
          const float* __restrict__ head_w,
          const float* __restrict__ head_b,
          float* __restrict__ out)
{
    extern __shared__ ull sh[];
    ull*   buf = sh;                        // BUFN ull
    float* fex = (float*)(sh + BUFN);
    float* cx  = fex + OFF_CX;
    float* sx  = fex + OFF_SX;
    float* tht = fex + OFF_THT;
    float* ths = fex + OFF_THS;
    float* red = fex + OFF_RED;
    float* zf  = fex + OFF_ZF;

    const int t = threadIdx.x;
    const int b = blockIdx.x;
    const int lane = t & 31, w = t >> 5;

    // ----- per-sample RX angles + shared shear tables -----
    if (t < NQ){
        float h = 0.5f * x[b * NQ + t];
        cx[t] = cosf(h);
        sx[t] = sinf(h);
    }
    if (t < NQ * DEPTH){
        float th = theta[t];
        tht[t] = -tanf(0.25f * th);      // -T
        ths[t] =  sinf(0.50f * th);      //  S
    }

    // ----- precompute CZ parity masks (layout A and C) -----
    unsigned czA = 0, czC = 0;
#pragma unroll
    for (int l = 0; l < AMPS; l++){
        int iA = (t << 5) | l;
        int iC = (l << 9) | t;
        czA |= (unsigned)(__popc(iA & (iA >> 1)) & 1) << l;
        czC |= (unsigned)(__popc(iC & (iC >> 1)) & 1) << l;
    }
    __syncthreads();

    // ----- initial product state, layout A -----
    ull amp[AMPS];
    float rT = 1.0f;
#pragma unroll
    for (int j = 0; j < 9; j++)
        rT *= ((t >> j) & 1) ? sx[8 - j] : cx[8 - j];   // phys bit 5+j -> qubit 8-j
    const int kT = __popc(t);
#pragma unroll
    for (int l = 0; l < AMPS; l++){
        float r = rT;
#pragma unroll
        for (int j = 0; j < 5; j++)
            r *= ((l >> j) & 1) ? sx[13 - j] : cx[13 - j];  // phys bit j -> qubit 13-j
        int k = (kT + __popc(l)) & 3;
        float re = (k == 0) ? r : ((k == 2) ? -r : 0.0f);
        float im = (k == 1) ? -r : ((k == 3) ? r : 0.0f);
        amp[l] = pack2(re, im);
    }

#define GATE(K, IDX) do { float nt_ = tht[(IDX)], s_ = ths[(IDX)]; \
        gate<K>(amp, pack2(nt_, nt_), pack2(s_, s_)); } while (0)
#define GATEH(K, SEL, PV, IDX) do { float nt_ = tht[(IDX)], s_ = ths[(IDX)]; \
        gate_half<K, SEL, PV>(amp, pack2(nt_, nt_), pack2(s_, s_)); } while (0)

    ull* segp = buf + SEG * w + lane;   // own B segment base
    ull* cp   = buf + 34 * w + lane;    // C-layout base (cross-segment)

    // ----- 6 layers; pipelined B<->C swaps split on phys bit 9 -----
#pragma unroll 1
    for (int d = 0; d < DEPTH; d += 2){
        int base = d * NQ;
        // ===== even layer: A -> [warp transpose] -> B -> [pipelined swap] -> C =====
        GATE(0, base + 13); GATE(1, base + 12); GATE(2, base + 11); GATE(3, base + 10); GATE(4, base + 9);
        transposeAB(buf, amp, t);
        GATE(0, base + 8);  GATE(1, base + 7);  GATE(2, base + 6);  GATE(3, base + 5);  GATE(4, base + 4);

        // --- pipelined B->C: half0 = B l<16 (phys bit9=0) == C even l ---
        __syncwarp();                       // own-tile cross-lane reads done
#pragma unroll
        for (int l = 0; l < 16; l++) segp[ROWP * l] = amp[l];
        __syncthreads();                    // bar1: all warps stored half0
#pragma unroll
        for (int l = 16; l < 32; l++) segp[ROWP * l] = amp[l];
#pragma unroll
        for (int l = 0; l < 32; l += 2) amp[l] = cp[544 * l];   // load C evens
        // C gates on bits 10-13 restricted to evens (bit9 = local bit0 = 0)
        GATEH(1, 0, 0, base + 3); GATEH(2, 0, 0, base + 2); GATEH(3, 0, 0, base + 1); GATEH(4, 0, 0, base + 0);
        __syncthreads();                    // bar2: all warps stored half1
#pragma unroll
        for (int l = 1; l < 32; l += 2) amp[l] = cp[544 * l];   // load C odds
        GATEH(1, 0, 1, base + 3); GATEH(2, 0, 1, base + 2); GATEH(3, 0, 1, base + 1); GATEH(4, 0, 1, base + 0);
        applyCZ(amp, czC);

        base += NQ;
        // ===== odd layer: C -> [pipelined swap] -> B -> [warp transpose] -> A =====
        GATE(0, base + 4);  GATE(1, base + 3);  GATE(2, base + 2);  GATE(3, base + 1);  GATE(4, base + 0);

        // --- pipelined C->B: store evens first (disjoint from any pending odd reads) ---
#pragma unroll
        for (int l = 0; l < 32; l += 2) cp[544 * l] = amp[l];
        __syncthreads();                    // bar1': all warps stored C evens (and finished odd reads)
#pragma unroll
        for (int l = 1; l < 32; l += 2) cp[544 * l] = amp[l];
#pragma unroll
        for (int l = 0; l < 16; l++) amp[l] = segp[ROWP * l];   // load B half0 (bit9=0)
        // B gates on bits 5-8 restricted to half0 (bit9 = local bit4 = 0)
        GATEH(0, 4, 0, base + 8); GATEH(1, 4, 0, base + 7); GATEH(2, 4, 0, base + 6); GATEH(3, 4, 0, base + 5);
        __syncthreads();                    // bar2': all warps stored C odds
#pragma unroll
        for (int l = 16; l < 32; l++) amp[l] = segp[ROWP * l];  // load B half1
        GATEH(0, 4, 1, base + 8); GATEH(1, 4, 1, base + 7); GATEH(2, 4, 1, base + 6); GATEH(3, 4, 1, base + 5);

        transposeAB(buf, amp, t);
        GATE(0, base + 13); GATE(1, base + 12); GATE(2, base + 11); GATE(3, base + 10); GATE(4, base + 9);
        applyCZ(amp, czA);
    }
#undef GATE
#undef GATEH

    // ----- epilogue: probs -> per-bit Z expectations -> head GEMV -----
    // State is in layout A: i = (t<<5) | l.
    float S = 0.0f;
    float zl0 = 0.f, zl1 = 0.f, zl2 = 0.f, zl3 = 0.f, zl4 = 0.f;
#pragma unroll
    for (int l = 0; l < AMPS; l++){
        float re, im; unpack2(amp[l], re, im);
        float pr = fmaf(re, re, im * im);
        S += pr;
        zl0 += (l & 1)  ? -pr : pr;
        zl1 += (l & 2)  ? -pr : pr;
        zl2 += (l & 4)  ? -pr : pr;
        zl3 += (l & 8)  ? -pr : pr;
        zl4 += (l & 16) ? -pr : pr;
    }
    float z[NQ];
    z[0] = zl0; z[1] = zl1; z[2] = zl2; z[3] = zl3; z[4] = zl4;
#pragma unroll
    for (int j = 0; j < 9; j++)
        z[5 + j] = ((t >> j) & 1) ? -S : S;

#pragma unroll
    for (int off = 16; off; off >>= 1)
#pragma unroll
        for (int p = 0; p < NQ; p++)
            z[p] += __shfl_xor_sync(0xFFFFFFFFu, z[p], off);

    if (lane == 0){
#pragma unroll
        for (int p = 0; p < NQ; p++) red[w * NQ + p] = z[p];
    }
    __syncthreads();
    if (t < NQ){
        float a = 0.0f;
#pragma unroll
        for (int ww = 0; ww < TPB / 32; ww++) a += red[ww * NQ + t];
        zf[t] = a;
    }
    __syncthreads();
    if (t < 2){
        float a = head_b[t];
#pragma unroll
        for (int p = 0; p < NQ; p++) a = fmaf(head_w[t * NQ + p], zf[p], a);
        out[b * 2 + t] = a;
    }
}

extern "C" void kernel_launch(void* const* d_in, const int* in_sizes, int n_in,
                              void* d_out, int out_size)
{
    const float* x      = (const float*)d_in[0];
    const float* theta  = (const float*)d_in[1];
    const float* head_w = (const float*)d_in[2];
    const float* head_b = (const float*)d_in[3];
    float* out = (float*)d_out;

    cudaFuncSetAttribute(qc_kernel, cudaFuncAttributeMaxDynamicSharedMemorySize, SMEM_BYTES);
    qc_kernel<<<512, TPB, SMEM_BYTES>>>(x, theta, head_w, head_b, out);
}